// round 7
// baseline (speedup 1.0000x reference)
#include <cuda_runtime.h>
#include <math.h>
#include <stdint.h>

#define HH 128
#define WW 128
#define HW 16384
#define NIMG 20
#define CHUNK 4

// ---------------- scratch (device globals; no allocation allowed) ----------------
__device__ float g_bufA[(size_t)NIMG * 64 * HW];
__device__ float g_bufB[(size_t)NIMG * 64 * HW];
__device__ float g_bufT[(size_t)NIMG * 64 * HW];
__device__ float g_off [(size_t)NIMG * 64 * HW];
__device__ float g_om  [(size_t)NIMG * 216 * HW];
__device__ float g_xT1 [(size_t)NIMG * HW * 64];   // transposed [img][px][ci]
__device__ float g_xT2 [(size_t)NIMG * HW * 64];
__device__ float g_feT [(size_t)NIMG * HW * 64];
__device__ float g_wprep[1327104];

// ---------------- helpers ----------------
__device__ __forceinline__ uint32_t smem_u32(const void* p) {
    uint32_t a;
    asm("{ .reg .u64 t; cvta.to.shared.u64 t, %1; cvt.u32.u64 %0, t; }" : "=r"(a) : "l"(p));
    return a;
}
__device__ __forceinline__ float to_tf32(float v) {
    unsigned u; asm("cvt.rna.tf32.f32 %0, %1;" : "=r"(u) : "f"(v));
    return __uint_as_float(u);
}
__device__ __forceinline__ void cp16(uint32_t dst, const void* src, unsigned nbytes) {
    asm volatile("cp.async.cg.shared.global [%0], [%1], 16, %2;"
                 :: "r"(dst), "l"(src), "r"(nbytes) : "memory");
}
__device__ __forceinline__ void cp_commit() {
    asm volatile("cp.async.commit_group;" ::: "memory");
}
__device__ __forceinline__ void cp_wait1() {
    asm volatile("cp.async.wait_group 1;" ::: "memory");
}
__device__ __forceinline__ void cp_wait0() {
    asm volatile("cp.async.wait_group 0;" ::: "memory");
}
__device__ __forceinline__ void mma_tf32(float* c, const float* a, const float* b) {
    asm volatile(
        "mma.sync.aligned.m16n8k8.row.col.f32.tf32.tf32.f32 "
        "{%0,%1,%2,%3}, {%4,%5,%6,%7}, {%8,%9}, {%0,%1,%2,%3};"
        : "+f"(c[0]), "+f"(c[1]), "+f"(c[2]), "+f"(c[3])
        : "r"(__float_as_uint(a[0])), "r"(__float_as_uint(a[1])),
          "r"(__float_as_uint(a[2])), "r"(__float_as_uint(a[3])),
          "r"(__float_as_uint(b[0])), "r"(__float_as_uint(b[1])));
}

// ---------------- single fused weight-prep kernel ----------------
// g_wprep layout:
//   [0, 368640)        res1[0..4], res2[0..4]   (conv 64->64, 36864 each)
//   [368640, 442368)   bn (conv 128->64, 73728)
//   [442368, 589824)   off[0..3] (conv 64->64)
//   [589824, 1179648)  com[0..3] (conv 64->216, 147456 each)
//   [1179648, 1327104) gemm[0..3] (36864 each)
__global__ void prep_all_kernel(const float* __restrict__ res_w1, const float* __restrict__ res_w2,
                                const float* __restrict__ w_bn,  const float* __restrict__ off_w,
                                const float* __restrict__ com_w, const float* __restrict__ dcn_w,
                                float* __restrict__ dst)
{
    const int gid = blockIdx.x * 256 + threadIdx.x;   // 1327104 total = 5184 * 256
    const float* src;
    int local, Cin, Cout;
    bool isGemm = false;
    if (gid < 368640) {
        const int ci = gid / 36864; local = gid - ci * 36864;
        src = (ci < 5) ? res_w1 + (size_t)ci * 36864 : res_w2 + (size_t)(ci - 5) * 36864;
        Cin = 64; Cout = 64;
    } else if (gid < 442368) {
        local = gid - 368640; src = w_bn; Cin = 128; Cout = 64;
    } else if (gid < 589824) {
        const int t = gid - 442368; const int d = t / 36864; local = t - d * 36864;
        src = off_w + (size_t)d * 36864; Cin = 64; Cout = 64;
    } else if (gid < 1179648) {
        const int t = gid - 589824; const int d = t / 147456; local = t - d * 147456;
        src = com_w + (size_t)d * 124416; Cin = 64; Cout = 216;
    } else {
        const int t = gid - 1179648; const int d = t / 36864; local = t - d * 36864;
        src = dcn_w + (size_t)d * 36864; isGemm = true; Cin = 64; Cout = 64;
    }
    float v;
    if (isGemm) {
        const int frag = local & 511;
        const int q    = frag & 3;
        const int lane = (frag >> 2) & 31;
        const int mi   = (frag >> 7) & 1;
        const int wM   = frag >> 8;
        const int chunk = local >> 9;
        const int g = chunk / 9, k = chunk - g * 9;
        const int co = wM * 32 + mi * 16 + ((q & 1) << 3) + (lane >> 2);
        const int ci = (lane & 3) + ((q >> 1) << 2);
        v = src[(size_t)co * 576 + (g * 8 + ci) * 9 + k];
    } else {
        const int q    = local & 3;
        const int lane = (local >> 2) & 31;
        const int mi   = (local >> 7) & 1;
        const int wM   = (local >> 8) & 1;
        const int s    = (local >> 9) & 1;
        const int kx   = (local >> 10) % 3;
        const int t    = local / 3072;
        const int nci16 = Cin >> 4;
        const int cc   = t % nci16;
        const int t2   = t / nci16;
        const int ky   = t2 % 3;
        const int zb   = t2 / 3;
        const int co   = zb * 64 + wM * 32 + mi * 16 + ((q & 1) << 3) + (lane >> 2);
        const int ci   = cc * 16 + s * 8 + (lane & 3) + ((q >> 1) << 2);
        v = (co < Cout) ? src[((size_t)co * Cin + ci) * 9 + ky * 3 + kx] : 0.f;
    }
    dst[gid] = to_tf32(v);
}

// ---------------- tf32 implicit-GEMM 3x3 SAME conv, 16-ci chunks ----------------
__global__ __launch_bounds__(256, 3) void conv3x3_tc2(
    const float* __restrict__ in, const float* __restrict__ wp,
    const float* __restrict__ bias, float* __restrict__ out,
    const float* __restrict__ addsrc, float* __restrict__ outT,
    int Cin, int Cout, int flags)
{
    __shared__ __align__(16) float sIn[2][2176];    // [ci(16)][136]: gc=0 at col 4
    __shared__ __align__(16) float sWq[2][3072];    // [kx(3)][s(2)][512]

    const int row  = blockIdx.x;
    const int img  = blockIdx.y;
    const int zb   = blockIdx.z;
    const int coT  = zb << 6;
    const int tid  = threadIdx.x;
    const int warp = tid >> 5;
    const int lane = tid & 31;
    const int g    = lane >> 2, t4 = lane & 3;
    const int wM   = warp & 1,  wN = warp >> 1;
    const int nci16 = Cin >> 4;
    const int nch  = 3 * nci16;
    const int catMode = flags & 4;

    const uint32_t sInB = smem_u32(sIn);
    const uint32_t sWB  = smem_u32(sWq);
    const float* inImg  = in + (size_t)img * (catMode ? 64 : Cin) * HW;
    const float* refImg = catMode ? in + (size_t)((img / 5) * 5 + 2) * 64 * HW : inImg;
    const float* wpL    = wp + (size_t)zb * nch * 3072;

    float acc[2][4][4];
#pragma unroll
    for (int i = 0; i < 2; i++)
#pragma unroll
        for (int j = 0; j < 4; j++)
#pragma unroll
            for (int l = 0; l < 4; l++) acc[i][j][l] = 0.f;

    if (tid < 64) {
        const int b = tid >> 5, r = tid & 31;
        sIn[b][(r >> 1) * 136 + ((r & 1) ? 132 : 3)] = 0.f;
    }

    auto loadChunk = [&](int c, int buf) {
        const int ky = c / nci16, cc = c - ky * nci16;
        int gr = row + ky - 1;
        const unsigned rs = ((unsigned)gr < HH) ? 16u : 0u;
        if (gr < 0) gr = 0; else if (gr > HH - 1) gr = HH - 1;
        const float* src;
        int ciBase;
        if (catMode) {
            if (cc < 4) { src = refImg; ciBase = cc * 16; }
            else        { src = inImg;  ciBase = (cc - 4) * 16; }
        } else { src = inImg; ciBase = cc * 16; }
#pragma unroll
        for (int i = tid; i < 512; i += 256) {
            const int ci = i >> 5, j = i & 31;
            cp16(sInB + (buf * 2176 + ci * 136 + 4 + 4 * j) * 4,
                 src + (size_t)(ciBase + ci) * HW + gr * WW + 4 * j, rs);
        }
        const float* ws = wpL + (size_t)c * 3072;
#pragma unroll
        for (int i = tid; i < 768; i += 256)
            cp16(sWB + (buf * 3072 + 4 * i) * 4, ws + 4 * i, 16);
        cp_commit();
    };

    loadChunk(0, 0);
    for (int c = 0; c < nch; c++) {
        const int buf = c & 1;
        if (c + 1 < nch) { loadChunk(c + 1, buf ^ 1); cp_wait1(); }
        else             { cp_wait0(); }
        __syncthreads();

        const float* sI  = sIn[buf];
        const float* sWb = sWq[buf];
#pragma unroll
        for (int kx = 0; kx < 3; kx++) {
#pragma unroll
            for (int s = 0; s < 2; s++) {
                const float4 a0 = *(const float4*)&sWb[kx * 1024 + s * 512 + wM * 256 + lane * 4];
                const float4 a1 = *(const float4*)&sWb[kx * 1024 + s * 512 + wM * 256 + 128 + lane * 4];
                const int bo = (s * 8 + t4) * 136 + 3 + kx + wN * 32 + g;
#pragma unroll
                for (int ni = 0; ni < 4; ni++) {
                    float b2[2] = { sI[bo + ni * 8], sI[bo + 544 + ni * 8] };
                    mma_tf32(acc[0][ni], (const float*)&a0, b2);
                    mma_tf32(acc[1][ni], (const float*)&a1, b2);
                }
            }
        }
        __syncthreads();
    }

    const int doRelu  = flags & 1;
    const int doRound = flags & 2;
#pragma unroll
    for (int mi = 0; mi < 2; mi++) {
#pragma unroll
        for (int rr = 0; rr < 2; rr++) {
            const int co = coT + wM * 32 + mi * 16 + rr * 8 + g;
            if (co < Cout) {
                const float bv = bias[co];
                const size_t base = ((size_t)img * Cout + co) * HW + row * WW + wN * 32 + 2 * t4;
#pragma unroll
                for (int ni = 0; ni < 4; ni++) {
                    float v0 = acc[mi][ni][rr * 2 + 0] + bv;
                    float v1 = acc[mi][ni][rr * 2 + 1] + bv;
                    const size_t idx = base + ni * 8;
                    if (addsrc) {
                        float2 r2 = *(const float2*)&addsrc[idx];
                        v0 += r2.x; v1 += r2.y;
                    }
                    if (doRelu) { v0 = fmaxf(v0, 0.f); v1 = fmaxf(v1, 0.f); }
                    if (doRound) { v0 = to_tf32(v0); v1 = to_tf32(v1); }
                    *(float2*)&out[idx] = make_float2(v0, v1);
                    if (outT) {
                        const int pxp = row * WW + wN * 32 + 2 * t4 + ni * 8;
                        outT[((size_t)img * HW + pxp) * 64 + co] = v0;
                        outT[((size_t)img * HW + pxp + 1) * 64 + co] = v1;
                    }
                }
            }
        }
    }
}

// ---------------- fused deformable-im2col + GEMM (Cout=64, K=576) ----------------
// Gathers read the TRANSPOSED input xT[img][px][ci] -> 1 LDG.128 per corner (4 ci).
__global__ __launch_bounds__(256, 3) void dcn_fused_kernel(
    const float* __restrict__ wp,   // [72][512] prepped
    const float* __restrict__ xT,   // [img][HW][64] transposed sampled input
    const float* __restrict__ om,   // [img][216][HW]
    const float* __restrict__ bias,
    float* __restrict__ out,        // [img][64][HW]
    float* __restrict__ outT)       // optional [img][HW][64]
{
    __shared__ __align__(16) float sB[2][1088];   // [ci(8)][136]
    __shared__ __align__(16) float sW[2][512];

    const int pxb  = blockIdx.x << 7;
    const int img  = blockIdx.y;
    const int tid  = threadIdx.x;
    const int warp = tid >> 5;
    const int lane = tid & 31;
    const int g_   = lane >> 2, t4 = lane & 3;
    const int wM   = warp & 1,  wN = warp >> 1;
    const int pxl  = tid & 127;
    const int half = tid >> 7;
    const int h    = pxb >> 7;
    const int w    = pxl;

    const uint32_t sWB = smem_u32(sW);
    const float* omj = om + (size_t)img * 216 * HW + pxb + pxl;
    const float* xTimg = xT + (size_t)img * HW * 64;

    float acc[2][4][4];
#pragma unroll
    for (int i = 0; i < 2; i++)
#pragma unroll
        for (int j = 0; j < 4; j++)
#pragma unroll
            for (int l = 0; l < 4; l++) acc[i][j][l] = 0.f;

    float rv[16];    // [corner(4)][ci(4)]
    float fw[4];

    auto gatherIssue = [&](int c) {
        const int gg = c / 9, k = c - gg * 9;
        const float dy = omj[(size_t)c * HW];
        const float dx = omj[(size_t)(72 + c) * HW];
        float m        = omj[(size_t)(144 + c) * HW];
        m = 1.f / (1.f + expf(-m));
        const float py  = (float)(h + k / 3 - 1) + dy;
        const float pxf = (float)(w + k % 3 - 1) + dx;
        const float y0f = floorf(py), x0f = floorf(pxf);
        const float wy = py - y0f, wx = pxf - x0f;
        const int y0 = (int)y0f, x0 = (int)x0f;
        const int y1 = y0 + 1,   x1 = x0 + 1;
        const bool vy0 = (y0 >= 0) & (y0 < HH), vy1 = (y1 >= 0) & (y1 < HH);
        const bool vx0 = (x0 >= 0) & (x0 < WW), vx1 = (x1 >= 0) & (x1 < WW);
        const int cy0 = min(max(y0, 0), HH - 1), cy1 = min(max(y1, 0), HH - 1);
        const int cx0 = min(max(x0, 0), WW - 1), cx1 = min(max(x1, 0), WW - 1);
        fw[0] = (1.f - wy) * (1.f - wx) * m * ((vy0 && vx0) ? 1.f : 0.f);
        fw[1] = (1.f - wy) * wx         * m * ((vy0 && vx1) ? 1.f : 0.f);
        fw[2] = wy * (1.f - wx)         * m * ((vy1 && vx0) ? 1.f : 0.f);
        fw[3] = wy * wx                 * m * ((vy1 && vx1) ? 1.f : 0.f);
        const int i00 = cy0 * WW + cx0, i01 = cy0 * WW + cx1;
        const int i10 = cy1 * WW + cx0, i11 = cy1 * WW + cx1;
        const int cio = gg * 8 + half * 4;
        *(float4*)&rv[0]  = *(const float4*)(xTimg + (size_t)i00 * 64 + cio);
        *(float4*)&rv[4]  = *(const float4*)(xTimg + (size_t)i01 * 64 + cio);
        *(float4*)&rv[8]  = *(const float4*)(xTimg + (size_t)i10 * 64 + cio);
        *(float4*)&rv[12] = *(const float4*)(xTimg + (size_t)i11 * 64 + cio);
    };
    auto stageW = [&](int c, int buf) {
        if (tid < 128)
            cp16(sWB + (buf * 512 + 4 * tid) * 4, wp + (size_t)c * 512 + 4 * tid, 16);
        cp_commit();
    };
    auto stsB = [&](int buf) {
#pragma unroll
        for (int cc = 0; cc < 4; cc++) {
            const float v = fw[0] * rv[cc] + fw[1] * rv[4 + cc]
                          + fw[2] * rv[8 + cc] + fw[3] * rv[12 + cc];
            sB[buf][(half * 4 + cc) * 136 + pxl] = to_tf32(v);
        }
    };

    stageW(0, 0);
    gatherIssue(0);
    stsB(0);
    cp_wait0();
    __syncthreads();

    for (int c = 0; c < 72; c++) {
        const int buf = c & 1;
        if (c < 71) { stageW(c + 1, buf ^ 1); gatherIssue(c + 1); }
        const float* sBb = sB[buf];
        const float* sWb = sW[buf];
        const float4 a0 = *(const float4*)&sWb[wM * 256 + lane * 4];
        const float4 a1 = *(const float4*)&sWb[wM * 256 + 128 + lane * 4];
        const int bo = t4 * 136 + wN * 32 + g_;
#pragma unroll
        for (int ni = 0; ni < 4; ni++) {
            float b2[2] = { sBb[bo + ni * 8], sBb[bo + 544 + ni * 8] };
            mma_tf32(acc[0][ni], (const float*)&a0, b2);
            mma_tf32(acc[1][ni], (const float*)&a1, b2);
        }
        if (c < 71) { stsB(buf ^ 1); cp_wait0(); }
        __syncthreads();
    }

#pragma unroll
    for (int mi = 0; mi < 2; mi++) {
#pragma unroll
        for (int rr = 0; rr < 2; rr++) {
            const int co = wM * 32 + mi * 16 + rr * 8 + g_;
            const float bv = bias[co];
            const size_t base = ((size_t)img * 64 + co) * HW + pxb + wN * 32 + 2 * t4;
#pragma unroll
            for (int ni = 0; ni < 4; ni++) {
                float v0 = to_tf32(acc[mi][ni][rr * 2 + 0] + bv);
                float v1 = to_tf32(acc[mi][ni][rr * 2 + 1] + bv);
                *(float2*)&out[base + ni * 8] = make_float2(v0, v1);
                if (outT) {
                    const int pxp = pxb + wN * 32 + 2 * t4 + ni * 8;
                    outT[((size_t)img * HW + pxp) * 64 + co] = v0;
                    outT[((size_t)img * HW + pxp + 1) * 64 + co] = v1;
                }
            }
        }
    }
}

// ---------------- FFMA 3x3 conv (Cin=1 / Cout=1 cases) ----------------
__global__ __launch_bounds__(256, 2) void conv3x3_kernel(
    const float* __restrict__ in, const float* __restrict__ wt,
    const float* __restrict__ bias, float* __restrict__ out,
    const float* __restrict__ addsrc,
    int Cin, int Cout, int doRelu, int doRound)
{
    __shared__ __align__(16) float sIn[CHUNK][18][80];
    __shared__ __align__(16) float sW[CHUNK][9][16];

    const int tw  = blockIdx.x & 1;
    const int th  = blockIdx.x >> 1;
    const int img = blockIdx.y;
    const int cob = blockIdx.z * 16;
    const int tid = threadIdx.x;
    const int tx  = tid & 15;
    const int ty  = tid >> 4;

    float acc[4][16];
#pragma unroll
    for (int p = 0; p < 4; p++)
#pragma unroll
        for (int c = 0; c < 16; c++) acc[p][c] = 0.f;

    const int nch = (Cin + CHUNK - 1) / CHUNK;
    for (int cc = 0; cc < nch; cc++) {
        const int cin0 = cc * CHUNK;
        for (int idx = tid; idx < CHUNK * 18 * 66; idx += 256) {
            int ci  = idx / (18 * 66);
            int rem = idx - ci * (18 * 66);
            int r = rem / 66, c = rem - r * 66;
            int gr = th * 16 + r - 1;
            int gc = tw * 64 + c - 1;
            int cin = cin0 + ci;
            float v = 0.f;
            if (cin < Cin && gr >= 0 && gr < HH && gc >= 0 && gc < WW)
                v = in[((size_t)img * Cin + cin) * HW + gr * WW + gc];
            sIn[ci][r][c] = v;
        }
        for (int idx = tid; idx < CHUNK * 9 * 16; idx += 256) {
            int ci  = idx / 144;
            int rem = idx - ci * 144;
            int k = rem >> 4, co = rem & 15;
            int cin = cin0 + ci;
            float v = 0.f;
            if (cin < Cin && (cob + co) < Cout)
                v = wt[((size_t)(cob + co) * Cin + cin) * 9 + k];
            sW[ci][k][co] = v;
        }
        __syncthreads();

        for (int ci = 0; ci < CHUNK; ci++) {
#pragma unroll
            for (int k = 0; k < 9; k++) {
                const int ky = k / 3, kx = k - ky * 3;
                const float4 w0 = *(const float4*)&sW[ci][k][0];
                const float4 w1 = *(const float4*)&sW[ci][k][4];
                const float4 w2 = *(const float4*)&sW[ci][k][8];
                const float4 w3 = *(const float4*)&sW[ci][k][12];
                const float wv[16] = {w0.x, w0.y, w0.z, w0.w, w1.x, w1.y, w1.z, w1.w,
                                      w2.x, w2.y, w2.z, w2.w, w3.x, w3.y, w3.z, w3.w};
#pragma unroll
                for (int p = 0; p < 4; p++) {
                    const float xv = sIn[ci][ty + ky][tx + 16 * p + kx];
#pragma unroll
                    for (int co = 0; co < 16; co++)
                        acc[p][co] = fmaf(xv, wv[co], acc[p][co]);
                }
            }
        }
        __syncthreads();
    }

    const int row = th * 16 + ty;
    const int colb2 = tw * 64 + tx;
#pragma unroll
    for (int co = 0; co < 16; co++) {
        const int oc = cob + co;
        if (oc < Cout) {
            const float b = bias[oc];
#pragma unroll
            for (int p = 0; p < 4; p++) {
                const size_t idx = ((size_t)img * Cout + oc) * HW + row * WW + colb2 + 16 * p;
                float v = acc[p][co] + b;
                if (addsrc) v += addsrc[idx];
                if (doRelu) v = fmaxf(v, 0.f);
                if (doRound) v = to_tf32(v);
                out[idx] = v;
            }
        }
    }
}

// ---------------- host launcher ----------------
static inline void launch_conv_ffma(const float* in, const float* w, const float* b,
                                    float* out, const float* add,
                                    int Cin, int Cout, int relu, int roundOut)
{
    dim3 grid(16, NIMG, (Cout + 15) / 16);
    conv3x3_kernel<<<grid, 256>>>(in, w, b, out, add, Cin, Cout, relu, roundOut);
}

static inline void launch_conv_tc(const float* in, const float* wp, const float* b,
                                  float* out, const float* add, float* outT,
                                  int Cin, int Cout, int flags)
{
    dim3 grid(HH, NIMG, (Cout + 63) / 64);
    conv3x3_tc2<<<grid, 256>>>(in, wp, b, out, add, outT, Cin, Cout, flags);
}

extern "C" void kernel_launch(void* const* d_in, const int* in_sizes, int n_in,
                              void* d_out, int out_size)
{
    const float* x       = (const float*)d_in[0];
    const float* w_init  = (const float*)d_in[1];
    const float* b_init  = (const float*)d_in[2];
    const float* res_w1  = (const float*)d_in[3];
    const float* res_b1  = (const float*)d_in[4];
    const float* res_w2  = (const float*)d_in[5];
    const float* res_b2  = (const float*)d_in[6];
    const float* w_bn    = (const float*)d_in[7];
    const float* b_bn    = (const float*)d_in[8];
    const float* off_w   = (const float*)d_in[9];
    const float* off_b   = (const float*)d_in[10];
    const float* com_w   = (const float*)d_in[11];
    const float* com_b   = (const float*)d_in[12];
    const float* dcn_w   = (const float*)d_in[13];
    const float* dcn_b   = (const float*)d_in[14];
    const float* w_rec   = (const float*)d_in[15];
    const float* b_rec   = (const float*)d_in[16];
    float* out = (float*)d_out;

    float *bufA, *bufB, *bufT, *obuf, *om, *xT1, *xT2, *feT, *wprep;
    cudaGetSymbolAddress((void**)&bufA, g_bufA);
    cudaGetSymbolAddress((void**)&bufB, g_bufB);
    cudaGetSymbolAddress((void**)&bufT, g_bufT);
    cudaGetSymbolAddress((void**)&obuf, g_off);
    cudaGetSymbolAddress((void**)&om,   g_om);
    cudaGetSymbolAddress((void**)&xT1,  g_xT1);
    cudaGetSymbolAddress((void**)&xT2,  g_xT2);
    cudaGetSymbolAddress((void**)&feT,  g_feT);
    cudaGetSymbolAddress((void**)&wprep, g_wprep);

    // ---- single fused weight prep ----
    prep_all_kernel<<<5184, 256>>>(res_w1, res_w2, w_bn, off_w, com_w, dcn_w, wprep);
    const float* pw_r1[5]; const float* pw_r2[5];
    for (int i = 0; i < 5; i++) { pw_r1[i] = wprep + (size_t)i * 36864; pw_r2[i] = wprep + (size_t)(5 + i) * 36864; }
    const float* pw_bn = wprep + 368640;
    const float* pw_off[4]; const float* pw_com[4]; const float* pw_gemm[4];
    for (int d = 0; d < 4; d++) {
        pw_off[d]  = wprep + 442368 + (size_t)d * 36864;
        pw_com[d]  = wprep + 589824 + (size_t)d * 147456;
        pw_gemm[d] = wprep + 1179648 + (size_t)d * 36864;
    }

    // ---- network ----
    // 1) init conv + relu (Cin=1, FFMA), round output to tf32
    launch_conv_ffma(x, w_init, b_init, bufA, nullptr, 1, 64, 1, 1);

    // 2) 5 residual blocks; last one also writes transposed feat (for DCN stage 2)
    float* cur = bufA;
    float* nxt = bufB;
    for (int i = 0; i < 5; i++) {
        launch_conv_tc(cur, pw_r1[i], res_b1 + i * 64, bufT, nullptr, nullptr, 64, 64, 1 | 2);
        launch_conv_tc(bufT, pw_r2[i], res_b2 + i * 64, nxt, cur,
                       (i == 4) ? feT : nullptr, 64, 64, 2);
        float* t = cur; cur = nxt; nxt = t;
    }
    float* feat = cur;

    // 3) bottleneck conv over [ref | nei]; also writes transposed (DCN stage 0's x)
    launch_conv_tc(feat, pw_bn, b_bn, bufA, nullptr, xT1, 128, 64, 2 | 4);

    // 4) four chained DCN stages
    dim3 ggemm(HW / 128, NIMG);
    auto dcn_stage = [&](const float* xTsrc, const float* feaSrc, int di,
                         float* outBuf, float* outTBuf) {
        launch_conv_tc(feaSrc, pw_off[di], off_b + di * 64, obuf, nullptr, nullptr, 64, 64, 2);
        launch_conv_tc(obuf, pw_com[di], com_b + di * 216, om, nullptr, nullptr, 64, 216, 0);
        dcn_fused_kernel<<<ggemm, 256>>>(pw_gemm[di], xTsrc, om, dcn_b + di * 64, outBuf, outTBuf);
    };

    dcn_stage(xT1, bufA, 0, bufT, xT2);      // fea = dcn(fea, o0); T for stage1
    dcn_stage(xT2, bufT, 1, bufA, nullptr);  // fea = dcn(fea, o1)
    dcn_stage(feT, bufA, 2, bufT, xT1);      // fea = dcn(nei, o2); T for stage3
    dcn_stage(xT1, bufT, 3, bufA, nullptr);  // aligned = dcn(fea, o3)

    // 5) reconstruction conv (Cout=1, FFMA) straight into d_out
    launch_conv_ffma(bufA, w_rec, b_rec, out, nullptr, 64, 1, 0, 0);
}

// round 8
// speedup vs baseline: 1.1030x; 1.1030x over previous
#include <cuda_runtime.h>
#include <math.h>
#include <stdint.h>

#define HH 128
#define WW 128
#define HW 16384
#define NIMG 20
#define CHUNK 4

// ---------------- scratch (device globals; no allocation allowed) ----------------
__device__ float g_bufA[(size_t)NIMG * 64 * HW];
__device__ float g_bufB[(size_t)NIMG * 64 * HW];
__device__ float g_bufT[(size_t)NIMG * 64 * HW];
__device__ float g_off [(size_t)NIMG * 64 * HW];
__device__ float g_om  [(size_t)NIMG * 216 * HW];
__device__ float g_wprep[1327104];

// ---------------- helpers ----------------
__device__ __forceinline__ uint32_t smem_u32(const void* p) {
    uint32_t a;
    asm("{ .reg .u64 t; cvta.to.shared.u64 t, %1; cvt.u32.u64 %0, t; }" : "=r"(a) : "l"(p));
    return a;
}
__device__ __forceinline__ float to_tf32(float v) {
    unsigned u; asm("cvt.rna.tf32.f32 %0, %1;" : "=r"(u) : "f"(v));
    return __uint_as_float(u);
}
__device__ __forceinline__ void cp16(uint32_t dst, const void* src, unsigned nbytes) {
    asm volatile("cp.async.cg.shared.global [%0], [%1], 16, %2;"
                 :: "r"(dst), "l"(src), "r"(nbytes) : "memory");
}
__device__ __forceinline__ void cp_commit() {
    asm volatile("cp.async.commit_group;" ::: "memory");
}
__device__ __forceinline__ void cp_wait1() {
    asm volatile("cp.async.wait_group 1;" ::: "memory");
}
__device__ __forceinline__ void cp_wait0() {
    asm volatile("cp.async.wait_group 0;" ::: "memory");
}
__device__ __forceinline__ void mma_tf32(float* c, const float* a, const float* b) {
    asm volatile(
        "mma.sync.aligned.m16n8k8.row.col.f32.tf32.tf32.f32 "
        "{%0,%1,%2,%3}, {%4,%5,%6,%7}, {%8,%9}, {%0,%1,%2,%3};"
        : "+f"(c[0]), "+f"(c[1]), "+f"(c[2]), "+f"(c[3])
        : "r"(__float_as_uint(a[0])), "r"(__float_as_uint(a[1])),
          "r"(__float_as_uint(a[2])), "r"(__float_as_uint(a[3])),
          "r"(__float_as_uint(b[0])), "r"(__float_as_uint(b[1])));
}

// ---------------- single fused weight-prep kernel ----------------
// conv chunk layout (per (zb,ky,cc8)): [kx(3)][wM(2)][mi(2)][lane(32)][q(4)] = 1536 floats
// gemm chunk layout (per (g,k)):       [wM(2)][mi(2)][lane(32)][q(4)]        = 512 floats
// g_wprep map:
//   [0, 368640)        res1[0..4], res2[0..4]   (36864 each)
//   [368640, 442368)   bn (128->64, 73728)
//   [442368, 589824)   off[0..3]
//   [589824, 1179648)  com[0..3] (147456 each)
//   [1179648, 1327104) gemm[0..3] (36864 each)
__global__ void prep_all_kernel(const float* __restrict__ res_w1, const float* __restrict__ res_w2,
                                const float* __restrict__ w_bn,  const float* __restrict__ off_w,
                                const float* __restrict__ com_w, const float* __restrict__ dcn_w,
                                float* __restrict__ dst)
{
    const int gid = blockIdx.x * 256 + threadIdx.x;   // 1327104 = 5184 * 256
    const float* src;
    int local, Cin, Cout;
    bool isGemm = false;
    if (gid < 368640) {
        const int ci = gid / 36864; local = gid - ci * 36864;
        src = (ci < 5) ? res_w1 + (size_t)ci * 36864 : res_w2 + (size_t)(ci - 5) * 36864;
        Cin = 64; Cout = 64;
    } else if (gid < 442368) {
        local = gid - 368640; src = w_bn; Cin = 128; Cout = 64;
    } else if (gid < 589824) {
        const int t = gid - 442368; const int d = t / 36864; local = t - d * 36864;
        src = off_w + (size_t)d * 36864; Cin = 64; Cout = 64;
    } else if (gid < 1179648) {
        const int t = gid - 589824; const int d = t / 147456; local = t - d * 147456;
        src = com_w + (size_t)d * 124416; Cin = 64; Cout = 216;
    } else {
        const int t = gid - 1179648; const int d = t / 36864; local = t - d * 36864;
        src = dcn_w + (size_t)d * 36864; isGemm = true; Cin = 64; Cout = 64;
    }
    float v;
    const int q    = local & 3;
    const int lane = (local >> 2) & 31;
    const int mi   = (local >> 7) & 1;
    const int wM   = (local >> 8) & 1;
    if (isGemm) {
        const int chunk = local >> 9;
        const int g = chunk / 9, k = chunk - g * 9;
        const int co = wM * 32 + mi * 16 + ((q & 1) << 3) + (lane >> 2);
        const int ci = (lane & 3) + ((q >> 1) << 2);
        v = src[(size_t)co * 576 + (g * 8 + ci) * 9 + k];
    } else {
        const int kx = (local >> 9) % 3;
        const int t  = local / 1536;
        const int nci8 = Cin >> 3;
        const int cc = t % nci8;
        const int t2 = t / nci8;
        const int ky = t2 % 3;
        const int zb = t2 / 3;
        const int co = zb * 64 + wM * 32 + mi * 16 + ((q & 1) << 3) + (lane >> 2);
        const int ci = cc * 8 + (lane & 3) + ((q >> 1) << 2);
        v = (co < Cout) ? src[((size_t)co * Cin + ci) * 9 + ky * 3 + kx] : 0.f;
    }
    dst[gid] = to_tf32(v);
}

// ---------------- tf32 implicit-GEMM 3x3 SAME conv, 2 output rows per block ----------------
// Block 256 thr = 8 warps (2 co x 4 px). Tile: 64 Cout x 256 px (2 rows). Chunk = (ky, 8 ci).
__global__ __launch_bounds__(256, 2) void conv3x3_tc2(
    const float* __restrict__ in, const float* __restrict__ wp,
    const float* __restrict__ bias, float* __restrict__ out,
    const float* __restrict__ addsrc, int Cin, int Cout, int flags)
{
    __shared__ __align__(16) float sIn[2][2176];    // [ci(8)][r(2)][136]: gc=0 at col 4
    __shared__ __align__(16) float sWq[2][1536];    // [kx(3)][512]

    const int row0 = blockIdx.x << 1;
    const int img  = blockIdx.y;
    const int zb   = blockIdx.z;
    const int coT  = zb << 6;
    const int tid  = threadIdx.x;
    const int warp = tid >> 5;
    const int lane = tid & 31;
    const int g    = lane >> 2, t4 = lane & 3;
    const int wM   = warp & 1,  wN = warp >> 1;
    const int nci8 = Cin >> 3;
    const int nch  = 3 * nci8;
    const int catMode = flags & 4;

    const uint32_t sInB = smem_u32(sIn);
    const uint32_t sWB  = smem_u32(sWq);
    const float* inImg  = in + (size_t)img * (catMode ? 64 : Cin) * HW;
    const float* refImg = catMode ? in + (size_t)((img / 5) * 5 + 2) * 64 * HW : inImg;
    const float* wpL    = wp + (size_t)zb * nch * 1536;

    float acc[2][2][4][4];   // [mi(co)][row][ni2(px)][c4]
#pragma unroll
    for (int i = 0; i < 2; i++)
#pragma unroll
        for (int r = 0; r < 2; r++)
#pragma unroll
            for (int j = 0; j < 4; j++)
#pragma unroll
                for (int l = 0; l < 4; l++) acc[i][r][j][l] = 0.f;

    // zero halo columns: 8ci x 2r x 2buf x 2cols = 64 threads
    if (tid < 64) {
        const int b = tid >> 5, rem = tid & 31;
        const int ci = rem >> 2, r = (rem >> 1) & 1, hcol = rem & 1;
        sIn[b][ci * 272 + r * 136 + (hcol ? 132 : 3)] = 0.f;
    }

    auto loadChunk = [&](int c, int buf) {
        const int ky = c / nci8, cc = c - ky * nci8;
        const float* src;
        int ciBase;
        if (catMode) {
            if (cc < 8) { src = refImg; ciBase = cc * 8; }
            else        { src = inImg;  ciBase = (cc - 8) * 8; }
        } else { src = inImg; ciBase = cc * 8; }
        // input: 8 ci x 2 rows x 32 float4 = 512 cp (2 per thread)
#pragma unroll
        for (int i = tid; i < 512; i += 256) {
            const int ci = i >> 6, rem = i & 63;
            const int r = rem >> 5, j = rem & 31;
            int gr = row0 + ky - 1 + r;
            const unsigned rs = ((unsigned)gr < HH) ? 16u : 0u;
            if (gr < 0) gr = 0; else if (gr > HH - 1) gr = HH - 1;
            cp16(sInB + (buf * 2176 + ci * 272 + r * 136 + 4 + 4 * j) * 4,
                 src + (size_t)(ciBase + ci) * HW + gr * WW + 4 * j, rs);
        }
        // weights: 384 float4
        const float* ws = wpL + (size_t)c * 1536;
#pragma unroll
        for (int i = tid; i < 384; i += 256)
            cp16(sWB + (buf * 1536 + 4 * i) * 4, ws + 4 * i, 16);
        cp_commit();
    };

    loadChunk(0, 0);
    for (int c = 0; c < nch; c++) {
        const int buf = c & 1;
        if (c + 1 < nch) { loadChunk(c + 1, buf ^ 1); cp_wait1(); }
        else             { cp_wait0(); }
        __syncthreads();

        const float* sI  = sIn[buf];
        const float* sWb = sWq[buf];
#pragma unroll
        for (int kx = 0; kx < 3; kx++) {
            const float4 a0 = *(const float4*)&sWb[kx * 512 + wM * 256 + lane * 4];
            const float4 a1 = *(const float4*)&sWb[kx * 512 + wM * 256 + 128 + lane * 4];
#pragma unroll
            for (int r = 0; r < 2; r++) {
                const int bo = t4 * 272 + r * 136 + 3 + kx + wN * 32 + g;
#pragma unroll
                for (int ni = 0; ni < 4; ni++) {
                    float b2[2] = { sI[bo + ni * 8], sI[bo + 1088 + ni * 8] };
                    mma_tf32(acc[0][r][ni], (const float*)&a0, b2);
                    mma_tf32(acc[1][r][ni], (const float*)&a1, b2);
                }
            }
        }
        __syncthreads();
    }

    const int doRelu  = flags & 1;
    const int doRound = flags & 2;
#pragma unroll
    for (int mi = 0; mi < 2; mi++) {
#pragma unroll
        for (int rr = 0; rr < 2; rr++) {
            const int co = coT + wM * 32 + mi * 16 + rr * 8 + g;
            if (co < Cout) {
                const float bv = bias[co];
#pragma unroll
                for (int r = 0; r < 2; r++) {
                    const size_t base = ((size_t)img * Cout + co) * HW + (row0 + r) * WW
                                      + wN * 32 + 2 * t4;
#pragma unroll
                    for (int ni = 0; ni < 4; ni++) {
                        float v0 = acc[mi][r][ni][rr * 2 + 0] + bv;
                        float v1 = acc[mi][r][ni][rr * 2 + 1] + bv;
                        const size_t idx = base + ni * 8;
                        if (addsrc) {
                            float2 r2 = *(const float2*)&addsrc[idx];
                            v0 += r2.x; v1 += r2.y;
                        }
                        if (doRelu) { v0 = fmaxf(v0, 0.f); v1 = fmaxf(v1, 0.f); }
                        if (doRound) { v0 = to_tf32(v0); v1 = to_tf32(v1); }
                        *(float2*)&out[idx] = make_float2(v0, v1);
                    }
                }
            }
        }
    }
}

// ---------------- fused deformable-im2col + GEMM (Cout=64, K=576) ----------------
__global__ __launch_bounds__(256, 3) void dcn_fused_kernel(
    const float* __restrict__ wp,   // [72][512] prepped
    const float* __restrict__ x,    // [img][64][HW] sampled input
    const float* __restrict__ om,   // [img][216][HW]
    const float* __restrict__ bias,
    float* __restrict__ out)        // [img][64][HW]
{
    __shared__ __align__(16) float sB[2][1088];   // [ci(8)][136]
    __shared__ __align__(16) float sW[2][512];

    const int pxb  = blockIdx.x << 7;
    const int img  = blockIdx.y;
    const int tid  = threadIdx.x;
    const int warp = tid >> 5;
    const int lane = tid & 31;
    const int g_   = lane >> 2, t4 = lane & 3;
    const int wM   = warp & 1,  wN = warp >> 1;
    const int pxl  = tid & 127;
    const int half = tid >> 7;
    const int h    = pxb >> 7;
    const int w    = pxl;

    const uint32_t sWB = smem_u32(sW);
    const float* omj = om + (size_t)img * 216 * HW + pxb + pxl;
    const float* xg  = x + (size_t)img * 64 * HW;

    float acc[2][4][4];
#pragma unroll
    for (int i = 0; i < 2; i++)
#pragma unroll
        for (int j = 0; j < 4; j++)
#pragma unroll
            for (int l = 0; l < 4; l++) acc[i][j][l] = 0.f;

    float rv[16];
    float fw[4];

    auto gatherIssue = [&](int c) {
        const int gg = c / 9, k = c - gg * 9;
        const float dy = omj[(size_t)c * HW];
        const float dx = omj[(size_t)(72 + c) * HW];
        float m        = omj[(size_t)(144 + c) * HW];
        m = 1.f / (1.f + expf(-m));
        const float py  = (float)(h + k / 3 - 1) + dy;
        const float pxf = (float)(w + k % 3 - 1) + dx;
        const float y0f = floorf(py), x0f = floorf(pxf);
        const float wy = py - y0f, wx = pxf - x0f;
        const int y0 = (int)y0f, x0 = (int)x0f;
        const int y1 = y0 + 1,   x1 = x0 + 1;
        const bool vy0 = (y0 >= 0) & (y0 < HH), vy1 = (y1 >= 0) & (y1 < HH);
        const bool vx0 = (x0 >= 0) & (x0 < WW), vx1 = (x1 >= 0) & (x1 < WW);
        const int cy0 = min(max(y0, 0), HH - 1), cy1 = min(max(y1, 0), HH - 1);
        const int cx0 = min(max(x0, 0), WW - 1), cx1 = min(max(x1, 0), WW - 1);
        fw[0] = (1.f - wy) * (1.f - wx) * m * ((vy0 && vx0) ? 1.f : 0.f);
        fw[1] = (1.f - wy) * wx         * m * ((vy0 && vx1) ? 1.f : 0.f);
        fw[2] = wy * (1.f - wx)         * m * ((vy1 && vx0) ? 1.f : 0.f);
        fw[3] = wy * wx                 * m * ((vy1 && vx1) ? 1.f : 0.f);
        const int i00 = cy0 * WW + cx0, i01 = cy0 * WW + cx1;
        const int i10 = cy1 * WW + cx0, i11 = cy1 * WW + cx1;
        const float* b = xg + (size_t)(gg * 8 + half * 4) * HW;
#pragma unroll
        for (int cc = 0; cc < 4; cc++) {
            const float* xc = b + (size_t)cc * HW;
            rv[cc * 4 + 0] = xc[i00];
            rv[cc * 4 + 1] = xc[i01];
            rv[cc * 4 + 2] = xc[i10];
            rv[cc * 4 + 3] = xc[i11];
        }
    };
    auto stageW = [&](int c, int buf) {
        if (tid < 128)
            cp16(sWB + (buf * 512 + 4 * tid) * 4, wp + (size_t)c * 512 + 4 * tid, 16);
        cp_commit();
    };
    auto stsB = [&](int buf) {
#pragma unroll
        for (int cc = 0; cc < 4; cc++) {
            const float v = fw[0] * rv[cc * 4] + fw[1] * rv[cc * 4 + 1]
                          + fw[2] * rv[cc * 4 + 2] + fw[3] * rv[cc * 4 + 3];
            sB[buf][(half * 4 + cc) * 136 + pxl] = to_tf32(v);
        }
    };

    stageW(0, 0);
    gatherIssue(0);
    stsB(0);
    cp_wait0();
    __syncthreads();

    for (int c = 0; c < 72; c++) {
        const int buf = c & 1;
        if (c < 71) { stageW(c + 1, buf ^ 1); gatherIssue(c + 1); }
        const float* sBb = sB[buf];
        const float* sWb = sW[buf];
        const float4 a0 = *(const float4*)&sWb[wM * 256 + lane * 4];
        const float4 a1 = *(const float4*)&sWb[wM * 256 + 128 + lane * 4];
        const int bo = t4 * 136 + wN * 32 + g_;
#pragma unroll
        for (int ni = 0; ni < 4; ni++) {
            float b2[2] = { sBb[bo + ni * 8], sBb[bo + 544 + ni * 8] };
            mma_tf32(acc[0][ni], (const float*)&a0, b2);
            mma_tf32(acc[1][ni], (const float*)&a1, b2);
        }
        if (c < 71) { stsB(buf ^ 1); cp_wait0(); }
        __syncthreads();
    }

#pragma unroll
    for (int mi = 0; mi < 2; mi++) {
#pragma unroll
        for (int rr = 0; rr < 2; rr++) {
            const int co = wM * 32 + mi * 16 + rr * 8 + g_;
            const float bv = bias[co];
            const size_t base = ((size_t)img * 64 + co) * HW + pxb + wN * 32 + 2 * t4;
#pragma unroll
            for (int ni = 0; ni < 4; ni++) {
                float v0 = to_tf32(acc[mi][ni][rr * 2 + 0] + bv);
                float v1 = to_tf32(acc[mi][ni][rr * 2 + 1] + bv);
                *(float2*)&out[base + ni * 8] = make_float2(v0, v1);
            }
        }
    }
}

// ---------------- FFMA 3x3 conv (Cin=1 / Cout=1 cases) ----------------
__global__ __launch_bounds__(256, 2) void conv3x3_kernel(
    const float* __restrict__ in, const float* __restrict__ wt,
    const float* __restrict__ bias, float* __restrict__ out,
    const float* __restrict__ addsrc,
    int Cin, int Cout, int doRelu, int doRound)
{
    __shared__ __align__(16) float sIn[CHUNK][18][80];
    __shared__ __align__(16) float sW[CHUNK][9][16];

    const int tw  = blockIdx.x & 1;
    const int th  = blockIdx.x >> 1;
    const int img = blockIdx.y;
    const int cob = blockIdx.z * 16;
    const int tid = threadIdx.x;
    const int tx  = tid & 15;
    const int ty  = tid >> 4;

    float acc[4][16];
#pragma unroll
    for (int p = 0; p < 4; p++)
#pragma unroll
        for (int c = 0; c < 16; c++) acc[p][c] = 0.f;

    const int nch = (Cin + CHUNK - 1) / CHUNK;
    for (int cc = 0; cc < nch; cc++) {
        const int cin0 = cc * CHUNK;
        for (int idx = tid; idx < CHUNK * 18 * 66; idx += 256) {
            int ci  = idx / (18 * 66);
            int rem = idx - ci * (18 * 66);
            int r = rem / 66, c = rem - r * 66;
            int gr = th * 16 + r - 1;
            int gc = tw * 64 + c - 1;
            int cin = cin0 + ci;
            float v = 0.f;
            if (cin < Cin && gr >= 0 && gr < HH && gc >= 0 && gc < WW)
                v = in[((size_t)img * Cin + cin) * HW + gr * WW + gc];
            sIn[ci][r][c] = v;
        }
        for (int idx = tid; idx < CHUNK * 9 * 16; idx += 256) {
            int ci  = idx / 144;
            int rem = idx - ci * 144;
            int k = rem >> 4, co = rem & 15;
            int cin = cin0 + ci;
            float v = 0.f;
            if (cin < Cin && (cob + co) < Cout)
                v = wt[((size_t)(cob + co) * Cin + cin) * 9 + k];
            sW[ci][k][co] = v;
        }
        __syncthreads();

        for (int ci = 0; ci < CHUNK; ci++) {
#pragma unroll
            for (int k = 0; k < 9; k++) {
                const int ky = k / 3, kx = k - ky * 3;
                const float4 w0 = *(const float4*)&sW[ci][k][0];
                const float4 w1 = *(const float4*)&sW[ci][k][4];
                const float4 w2 = *(const float4*)&sW[ci][k][8];
                const float4 w3 = *(const float4*)&sW[ci][k][12];
                const float wv[16] = {w0.x, w0.y, w0.z, w0.w, w1.x, w1.y, w1.z, w1.w,
                                      w2.x, w2.y, w2.z, w2.w, w3.x, w3.y, w3.z, w3.w};
#pragma unroll
                for (int p = 0; p < 4; p++) {
                    const float xv = sIn[ci][ty + ky][tx + 16 * p + kx];
#pragma unroll
                    for (int co = 0; co < 16; co++)
                        acc[p][co] = fmaf(xv, wv[co], acc[p][co]);
                }
            }
        }
        __syncthreads();
    }

    const int row = th * 16 + ty;
    const int colb2 = tw * 64 + tx;
#pragma unroll
    for (int co = 0; co < 16; co++) {
        const int oc = cob + co;
        if (oc < Cout) {
            const float b = bias[oc];
#pragma unroll
            for (int p = 0; p < 4; p++) {
                const size_t idx = ((size_t)img * Cout + oc) * HW + row * WW + colb2 + 16 * p;
                float v = acc[p][co] + b;
                if (addsrc) v += addsrc[idx];
                if (doRelu) v = fmaxf(v, 0.f);
                if (doRound) v = to_tf32(v);
                out[idx] = v;
            }
        }
    }
}

// ---------------- host launcher ----------------
static inline void launch_conv_ffma(const float* in, const float* w, const float* b,
                                    float* out, const float* add,
                                    int Cin, int Cout, int relu, int roundOut)
{
    dim3 grid(16, NIMG, (Cout + 15) / 16);
    conv3x3_kernel<<<grid, 256>>>(in, w, b, out, add, Cin, Cout, relu, roundOut);
}

static inline void launch_conv_tc(const float* in, const float* wp, const float* b,
                                  float* out, const float* add,
                                  int Cin, int Cout, int flags)
{
    dim3 grid(HH / 2, NIMG, (Cout + 63) / 64);
    conv3x3_tc2<<<grid, 256>>>(in, wp, b, out, add, Cin, Cout, flags);
}

extern "C" void kernel_launch(void* const* d_in, const int* in_sizes, int n_in,
                              void* d_out, int out_size)
{
    const float* x       = (const float*)d_in[0];
    const float* w_init  = (const float*)d_in[1];
    const float* b_init  = (const float*)d_in[2];
    const float* res_w1  = (const float*)d_in[3];
    const float* res_b1  = (const float*)d_in[4];
    const float* res_w2  = (const float*)d_in[5];
    const float* res_b2  = (const float*)d_in[6];
    const float* w_bn    = (const float*)d_in[7];
    const float* b_bn    = (const float*)d_in[8];
    const float* off_w   = (const float*)d_in[9];
    const float* off_b   = (const float*)d_in[10];
    const float* com_w   = (const float*)d_in[11];
    const float* com_b   = (const float*)d_in[12];
    const float* dcn_w   = (const float*)d_in[13];
    const float* dcn_b   = (const float*)d_in[14];
    const float* w_rec   = (const float*)d_in[15];
    const float* b_rec   = (const float*)d_in[16];
    float* out = (float*)d_out;

    float *bufA, *bufB, *bufT, *obuf, *om, *wprep;
    cudaGetSymbolAddress((void**)&bufA, g_bufA);
    cudaGetSymbolAddress((void**)&bufB, g_bufB);
    cudaGetSymbolAddress((void**)&bufT, g_bufT);
    cudaGetSymbolAddress((void**)&obuf, g_off);
    cudaGetSymbolAddress((void**)&om,   g_om);
    cudaGetSymbolAddress((void**)&wprep, g_wprep);

    // ---- single fused weight prep ----
    prep_all_kernel<<<5184, 256>>>(res_w1, res_w2, w_bn, off_w, com_w, dcn_w, wprep);
    const float* pw_r1[5]; const float* pw_r2[5];
    for (int i = 0; i < 5; i++) { pw_r1[i] = wprep + (size_t)i * 36864; pw_r2[i] = wprep + (size_t)(5 + i) * 36864; }
    const float* pw_bn = wprep + 368640;
    const float* pw_off[4]; const float* pw_com[4]; const float* pw_gemm[4];
    for (int d = 0; d < 4; d++) {
        pw_off[d]  = wprep + 442368 + (size_t)d * 36864;
        pw_com[d]  = wprep + 589824 + (size_t)d * 147456;
        pw_gemm[d] = wprep + 1179648 + (size_t)d * 36864;
    }

    // ---- network ----
    // 1) init conv + relu (Cin=1, FFMA), round output to tf32
    launch_conv_ffma(x, w_init, b_init, bufA, nullptr, 1, 64, 1, 1);

    // 2) 5 residual blocks
    float* cur = bufA;
    float* nxt = bufB;
    for (int i = 0; i < 5; i++) {
        launch_conv_tc(cur, pw_r1[i], res_b1 + i * 64, bufT, nullptr, 64, 64, 1 | 2);
        launch_conv_tc(bufT, pw_r2[i], res_b2 + i * 64, nxt, cur, 64, 64, 2);
        float* t = cur; cur = nxt; nxt = t;
    }
    float* feat = cur;

    // 3) bottleneck conv over [ref | nei] (cat folded into loads)
    launch_conv_tc(feat, pw_bn, b_bn, bufA, nullptr, 128, 64, 2 | 4);

    // 4) four chained DCN stages
    dim3 ggemm(HW / 128, NIMG);
    auto dcn_stage = [&](const float* xsrc, const float* feaSrc, int di, float* outBuf) {
        launch_conv_tc(feaSrc, pw_off[di], off_b + di * 64, obuf, nullptr, 64, 64, 2);
        launch_conv_tc(obuf, pw_com[di], com_b + di * 216, om, nullptr, 64, 216, 0);
        dcn_fused_kernel<<<ggemm, 256>>>(pw_gemm[di], xsrc, om, dcn_b + di * 64, outBuf);
    };

    dcn_stage(bufA, bufA, 0, bufT);   // fea = dcn(fea, o0)
    dcn_stage(bufT, bufT, 1, bufA);   // fea = dcn(fea, o1)
    dcn_stage(feat, bufA, 2, bufT);   // fea = dcn(nei, o2)
    dcn_stage(bufT, bufT, 3, bufA);   // aligned = dcn(fea, o3)

    // 5) reconstruction conv (Cout=1, FFMA) straight into d_out
    launch_conv_ffma(bufA, w_rec, b_rec, out, nullptr, 64, 1, 0, 0);
}

// round 9
// speedup vs baseline: 1.2628x; 1.1448x over previous
#include <cuda_runtime.h>
#include <math.h>
#include <stdint.h>

#define HH 128
#define WW 128
#define HW 16384
#define NIMG 20
#define CHUNK 4

// ---------------- scratch (device globals; no allocation allowed) ----------------
__device__ float g_bufA[(size_t)NIMG * 64 * HW];
__device__ float g_bufB[(size_t)NIMG * 64 * HW];
__device__ float g_bufT[(size_t)NIMG * 64 * HW];
__device__ float g_off [(size_t)NIMG * 64 * HW];
__device__ float g_om  [(size_t)NIMG * 216 * HW];
__device__ float g_wprep[1327104];

// ---------------- helpers ----------------
__device__ __forceinline__ uint32_t smem_u32(const void* p) {
    uint32_t a;
    asm("{ .reg .u64 t; cvta.to.shared.u64 t, %1; cvt.u32.u64 %0, t; }" : "=r"(a) : "l"(p));
    return a;
}
__device__ __forceinline__ float to_tf32(float v) {
    unsigned u; asm("cvt.rna.tf32.f32 %0, %1;" : "=r"(u) : "f"(v));
    return __uint_as_float(u);
}
__device__ __forceinline__ void cp16(uint32_t dst, const void* src, unsigned nbytes) {
    asm volatile("cp.async.cg.shared.global [%0], [%1], 16, %2;"
                 :: "r"(dst), "l"(src), "r"(nbytes) : "memory");
}
__device__ __forceinline__ void cp_commit() {
    asm volatile("cp.async.commit_group;" ::: "memory");
}
__device__ __forceinline__ void cp_wait1() {
    asm volatile("cp.async.wait_group 1;" ::: "memory");
}
__device__ __forceinline__ void cp_wait0() {
    asm volatile("cp.async.wait_group 0;" ::: "memory");
}
__device__ __forceinline__ void mma_tf32(float* c, const float* a, const float* b) {
    asm volatile(
        "mma.sync.aligned.m16n8k8.row.col.f32.tf32.tf32.f32 "
        "{%0,%1,%2,%3}, {%4,%5,%6,%7}, {%8,%9}, {%0,%1,%2,%3};"
        : "+f"(c[0]), "+f"(c[1]), "+f"(c[2]), "+f"(c[3])
        : "r"(__float_as_uint(a[0])), "r"(__float_as_uint(a[1])),
          "r"(__float_as_uint(a[2])), "r"(__float_as_uint(a[3])),
          "r"(__float_as_uint(b[0])), "r"(__float_as_uint(b[1])));
}

// ---------------- single fused weight-prep kernel ----------------
// conv chunk layout (per (zb,ky,cc16)): [kx(3)][s(2)][wM(2)][mi(2)][lane(32)][q(4)] = 3072 floats
// gemm chunk layout (per (g,k)):        [wM(2)][mi(2)][lane(32)][q(4)]              = 512 floats
// g_wprep map:
//   [0, 368640)        res1[0..4], res2[0..4]   (36864 each)
//   [368640, 442368)   bn (128->64, 73728)
//   [442368, 589824)   off[0..3] (36864 each)
//   [589824, 1179648)  com[0..3] (147456 each)
//   [1179648, 1327104) gemm[0..3] (36864 each)
__global__ void prep_all_kernel(const float* __restrict__ res_w1, const float* __restrict__ res_w2,
                                const float* __restrict__ w_bn,  const float* __restrict__ off_w,
                                const float* __restrict__ com_w, const float* __restrict__ dcn_w,
                                float* __restrict__ dst)
{
    const int gid = blockIdx.x * 256 + threadIdx.x;   // 1327104 = 5184 * 256
    const float* src;
    int local, Cin, Cout;
    bool isGemm = false;
    if (gid < 368640) {
        const int ci = gid / 36864; local = gid - ci * 36864;
        src = (ci < 5) ? res_w1 + (size_t)ci * 36864 : res_w2 + (size_t)(ci - 5) * 36864;
        Cin = 64; Cout = 64;
    } else if (gid < 442368) {
        local = gid - 368640; src = w_bn; Cin = 128; Cout = 64;
    } else if (gid < 589824) {
        const int t = gid - 442368; const int d = t / 36864; local = t - d * 36864;
        src = off_w + (size_t)d * 36864; Cin = 64; Cout = 64;
    } else if (gid < 1179648) {
        const int t = gid - 589824; const int d = t / 147456; local = t - d * 147456;
        src = com_w + (size_t)d * 124416; Cin = 64; Cout = 216;
    } else {
        const int t = gid - 1179648; const int d = t / 36864; local = t - d * 36864;
        src = dcn_w + (size_t)d * 36864; isGemm = true; Cin = 64; Cout = 64;
    }
    float v;
    const int q    = local & 3;
    const int lane = (local >> 2) & 31;
    const int mi   = (local >> 7) & 1;
    const int wM   = (local >> 8) & 1;
    if (isGemm) {
        const int chunk = local >> 9;
        const int g = chunk / 9, k = chunk - g * 9;
        const int co = wM * 32 + mi * 16 + ((q & 1) << 3) + (lane >> 2);
        const int ci = (lane & 3) + ((q >> 1) << 2);
        v = src[(size_t)co * 576 + (g * 8 + ci) * 9 + k];
    } else {
        const int s  = (local >> 9) & 1;
        const int kx = (local >> 10) % 3;
        const int t  = local / 3072;
        const int nci16 = Cin >> 4;
        const int cc = t % nci16;
        const int t2 = t / nci16;
        const int ky = t2 % 3;
        const int zb = t2 / 3;
        const int co = zb * 64 + wM * 32 + mi * 16 + ((q & 1) << 3) + (lane >> 2);
        const int ci = cc * 16 + s * 8 + (lane & 3) + ((q >> 1) << 2);
        v = (co < Cout) ? src[((size_t)co * Cin + ci) * 9 + ky * 3 + kx] : 0.f;
    }
    dst[gid] = to_tf32(v);
}

// ---------------- tf32 implicit-GEMM 3x3 SAME conv, 16-ci chunks ----------------
// Block 256 thr = 8 warps (2M x 4N). Tile: 64 Cout x 128 px (one row). Chunk = (ky, 16 ci).
__global__ __launch_bounds__(256, 3) void conv3x3_tc2(
    const float* __restrict__ in, const float* __restrict__ wp,
    const float* __restrict__ bias, float* __restrict__ out,
    const float* __restrict__ addsrc, int Cin, int Cout, int flags)
{
    __shared__ __align__(16) float sIn[2][2176];    // [ci(16)][136]: gc=0 at col 4
    __shared__ __align__(16) float sWq[2][3072];    // [kx(3)][s(2)][512]

    const int row  = blockIdx.x;
    const int img  = blockIdx.y;
    const int zb   = blockIdx.z;
    const int coT  = zb << 6;
    const int tid  = threadIdx.x;
    const int warp = tid >> 5;
    const int lane = tid & 31;
    const int g    = lane >> 2, t4 = lane & 3;
    const int wM   = warp & 1,  wN = warp >> 1;
    const int nci16 = Cin >> 4;
    const int nch  = 3 * nci16;
    const int catMode = flags & 4;

    const uint32_t sInB = smem_u32(sIn);
    const uint32_t sWB  = smem_u32(sWq);
    const float* inImg  = in + (size_t)img * (catMode ? 64 : Cin) * HW;
    const float* refImg = catMode ? in + (size_t)((img / 5) * 5 + 2) * 64 * HW : inImg;
    const float* wpL    = wp + (size_t)zb * nch * 3072;

    float acc[2][4][4];
#pragma unroll
    for (int i = 0; i < 2; i++)
#pragma unroll
        for (int j = 0; j < 4; j++)
#pragma unroll
            for (int l = 0; l < 4; l++) acc[i][j][l] = 0.f;

    if (tid < 64) {
        const int b = tid >> 5, r = tid & 31;
        sIn[b][(r >> 1) * 136 + ((r & 1) ? 132 : 3)] = 0.f;
    }

    auto loadChunk = [&](int c, int buf) {
        const int ky = c / nci16, cc = c - ky * nci16;
        int gr = row + ky - 1;
        const unsigned rs = ((unsigned)gr < HH) ? 16u : 0u;
        if (gr < 0) gr = 0; else if (gr > HH - 1) gr = HH - 1;
        const float* src;
        int ciBase;
        if (catMode) {
            if (cc < 4) { src = refImg; ciBase = cc * 16; }
            else        { src = inImg;  ciBase = (cc - 4) * 16; }
        } else { src = inImg; ciBase = cc * 16; }
#pragma unroll
        for (int i = tid; i < 512; i += 256) {
            const int ci = i >> 5, j = i & 31;
            cp16(sInB + (buf * 2176 + ci * 136 + 4 + 4 * j) * 4,
                 src + (size_t)(ciBase + ci) * HW + gr * WW + 4 * j, rs);
        }
        const float* ws = wpL + (size_t)c * 3072;
#pragma unroll
        for (int i = tid; i < 768; i += 256)
            cp16(sWB + (buf * 3072 + 4 * i) * 4, ws + 4 * i, 16);
        cp_commit();
    };

    loadChunk(0, 0);
    for (int c = 0; c < nch; c++) {
        const int buf = c & 1;
        if (c + 1 < nch) { loadChunk(c + 1, buf ^ 1); cp_wait1(); }
        else             { cp_wait0(); }
        __syncthreads();

        const float* sI  = sIn[buf];
        const float* sWb = sWq[buf];
#pragma unroll
        for (int kx = 0; kx < 3; kx++) {
#pragma unroll
            for (int s = 0; s < 2; s++) {
                const float4 a0 = *(const float4*)&sWb[kx * 1024 + s * 512 + wM * 256 + lane * 4];
                const float4 a1 = *(const float4*)&sWb[kx * 1024 + s * 512 + wM * 256 + 128 + lane * 4];
                const int bo = (s * 8 + t4) * 136 + 3 + kx + wN * 32 + g;
#pragma unroll
                for (int ni = 0; ni < 4; ni++) {
                    float b2[2] = { sI[bo + ni * 8], sI[bo + 544 + ni * 8] };
                    mma_tf32(acc[0][ni], (const float*)&a0, b2);
                    mma_tf32(acc[1][ni], (const float*)&a1, b2);
                }
            }
        }
        __syncthreads();
    }

    const int doRelu  = flags & 1;
    const int doRound = flags & 2;
#pragma unroll
    for (int mi = 0; mi < 2; mi++) {
#pragma unroll
        for (int rr = 0; rr < 2; rr++) {
            const int co = coT + wM * 32 + mi * 16 + rr * 8 + g;
            if (co < Cout) {
                const float bv = bias[co];
                const size_t base = ((size_t)img * Cout + co) * HW + row * WW + wN * 32 + 2 * t4;
#pragma unroll
                for (int ni = 0; ni < 4; ni++) {
                    float v0 = acc[mi][ni][rr * 2 + 0] + bv;
                    float v1 = acc[mi][ni][rr * 2 + 1] + bv;
                    const size_t idx = base + ni * 8;
                    if (addsrc) {
                        float2 r2 = *(const float2*)&addsrc[idx];
                        v0 += r2.x; v1 += r2.y;
                    }
                    if (doRelu) { v0 = fmaxf(v0, 0.f); v1 = fmaxf(v1, 0.f); }
                    if (doRound) { v0 = to_tf32(v0); v1 = to_tf32(v1); }
                    *(float2*)&out[idx] = make_float2(v0, v1);
                }
            }
        }
    }
}

// ---------------- fused deformable-im2col + GEMM (Cout=64, K=576) ----------------
// Block 256. Tile: 64 co x 128 px (one image row). K chunk = one (g,k): 8 channels.
__global__ __launch_bounds__(256, 3) void dcn_fused_kernel(
    const float* __restrict__ wp,   // [72][512] prepped
    const float* __restrict__ x,    // [img][64][HW] sampled input
    const float* __restrict__ om,   // [img][216][HW]
    const float* __restrict__ bias,
    float* __restrict__ out)        // [img][64][HW]
{
    __shared__ __align__(16) float sB[2][1088];   // [ci(8)][136]
    __shared__ __align__(16) float sW[2][512];

    const int pxb  = blockIdx.x << 7;
    const int img  = blockIdx.y;
    const int tid  = threadIdx.x;
    const int warp = tid >> 5;
    const int lane = tid & 31;
    const int g_   = lane >> 2, t4 = lane & 3;
    const int wM   = warp & 1,  wN = warp >> 1;
    const int pxl  = tid & 127;
    const int half = tid >> 7;
    const int h    = pxb >> 7;
    const int w    = pxl;

    const uint32_t sWB = smem_u32(sW);
    const float* omj = om + (size_t)img * 216 * HW + pxb + pxl;
    const float* xg  = x + (size_t)img * 64 * HW;

    float acc[2][4][4];
#pragma unroll
    for (int i = 0; i < 2; i++)
#pragma unroll
        for (int j = 0; j < 4; j++)
#pragma unroll
            for (int l = 0; l < 4; l++) acc[i][j][l] = 0.f;

    float rv[16];
    float fw[4];

    auto gatherIssue = [&](int c) {
        const int gg = c / 9, k = c - gg * 9;
        const float dy = omj[(size_t)c * HW];
        const float dx = omj[(size_t)(72 + c) * HW];
        float m        = omj[(size_t)(144 + c) * HW];
        m = 1.f / (1.f + expf(-m));
        const float py  = (float)(h + k / 3 - 1) + dy;
        const float pxf = (float)(w + k % 3 - 1) + dx;
        const float y0f = floorf(py), x0f = floorf(pxf);
        const float wy = py - y0f, wx = pxf - x0f;
        const int y0 = (int)y0f, x0 = (int)x0f;
        const int y1 = y0 + 1,   x1 = x0 + 1;
        const bool vy0 = (y0 >= 0) & (y0 < HH), vy1 = (y1 >= 0) & (y1 < HH);
        const bool vx0 = (x0 >= 0) & (x0 < WW), vx1 = (x1 >= 0) & (x1 < WW);
        const int cy0 = min(max(y0, 0), HH - 1), cy1 = min(max(y1, 0), HH - 1);
        const int cx0 = min(max(x0, 0), WW - 1), cx1 = min(max(x1, 0), WW - 1);
        fw[0] = (1.f - wy) * (1.f - wx) * m * ((vy0 && vx0) ? 1.f : 0.f);
        fw[1] = (1.f - wy) * wx         * m * ((vy0 && vx1) ? 1.f : 0.f);
        fw[2] = wy * (1.f - wx)         * m * ((vy1 && vx0) ? 1.f : 0.f);
        fw[3] = wy * wx                 * m * ((vy1 && vx1) ? 1.f : 0.f);
        const int i00 = cy0 * WW + cx0, i01 = cy0 * WW + cx1;
        const int i10 = cy1 * WW + cx0, i11 = cy1 * WW + cx1;
        const float* b = xg + (size_t)(gg * 8 + half * 4) * HW;
#pragma unroll
        for (int cc = 0; cc < 4; cc++) {
            const float* xc = b + (size_t)cc * HW;
            rv[cc * 4 + 0] = xc[i00];
            rv[cc * 4 + 1] = xc[i01];
            rv[cc * 4 + 2] = xc[i10];
            rv[cc * 4 + 3] = xc[i11];
        }
    };
    auto stageW = [&](int c, int buf) {
        if (tid < 128)
            cp16(sWB + (buf * 512 + 4 * tid) * 4, wp + (size_t)c * 512 + 4 * tid, 16);
        cp_commit();
    };
    auto stsB = [&](int buf) {
#pragma unroll
        for (int cc = 0; cc < 4; cc++) {
            const float v = fw[0] * rv[cc * 4] + fw[1] * rv[cc * 4 + 1]
                          + fw[2] * rv[cc * 4 + 2] + fw[3] * rv[cc * 4 + 3];
            sB[buf][(half * 4 + cc) * 136 + pxl] = to_tf32(v);
        }
    };

    stageW(0, 0);
    gatherIssue(0);
    stsB(0);
    cp_wait0();
    __syncthreads();

    for (int c = 0; c < 72; c++) {
        const int buf = c & 1;
        if (c < 71) { stageW(c + 1, buf ^ 1); gatherIssue(c + 1); }
        const float* sBb = sB[buf];
        const float* sWb = sW[buf];
        const float4 a0 = *(const float4*)&sWb[wM * 256 + lane * 4];
        const float4 a1 = *(const float4*)&sWb[wM * 256 + 128 + lane * 4];
        const int bo = t4 * 136 + wN * 32 + g_;
#pragma unroll
        for (int ni = 0; ni < 4; ni++) {
            float b2[2] = { sBb[bo + ni * 8], sBb[bo + 544 + ni * 8] };
            mma_tf32(acc[0][ni], (const float*)&a0, b2);
            mma_tf32(acc[1][ni], (const float*)&a1, b2);
        }
        if (c < 71) { stsB(buf ^ 1); cp_wait0(); }
        __syncthreads();
    }

#pragma unroll
    for (int mi = 0; mi < 2; mi++) {
#pragma unroll
        for (int rr = 0; rr < 2; rr++) {
            const int co = wM * 32 + mi * 16 + rr * 8 + g_;
            const float bv = bias[co];
            const size_t base = ((size_t)img * 64 + co) * HW + pxb + wN * 32 + 2 * t4;
#pragma unroll
            for (int ni = 0; ni < 4; ni++) {
                float v0 = to_tf32(acc[mi][ni][rr * 2 + 0] + bv);
                float v1 = to_tf32(acc[mi][ni][rr * 2 + 1] + bv);
                *(float2*)&out[base + ni * 8] = make_float2(v0, v1);
            }
        }
    }
}

// ---------------- FFMA 3x3 conv (Cin=1 / Cout=1 cases) ----------------
__global__ __launch_bounds__(256, 2) void conv3x3_kernel(
    const float* __restrict__ in, const float* __restrict__ wt,
    const float* __restrict__ bias, float* __restrict__ out,
    const float* __restrict__ addsrc,
    int Cin, int Cout, int doRelu, int doRound)
{
    __shared__ __align__(16) float sIn[CHUNK][18][80];
    __shared__ __align__(16) float sW[CHUNK][9][16];

    const int tw  = blockIdx.x & 1;
    const int th  = blockIdx.x >> 1;
    const int img = blockIdx.y;
    const int cob = blockIdx.z * 16;
    const int tid = threadIdx.x;
    const int tx  = tid & 15;
    const int ty  = tid >> 4;

    float acc[4][16];
#pragma unroll
    for (int p = 0; p < 4; p++)
#pragma unroll
        for (int c = 0; c < 16; c++) acc[p][c] = 0.f;

    const int nch = (Cin + CHUNK - 1) / CHUNK;
    for (int cc = 0; cc < nch; cc++) {
        const int cin0 = cc * CHUNK;
        for (int idx = tid; idx < CHUNK * 18 * 66; idx += 256) {
            int ci  = idx / (18 * 66);
            int rem = idx - ci * (18 * 66);
            int r = rem / 66, c = rem - r * 66;
            int gr = th * 16 + r - 1;
            int gc = tw * 64 + c - 1;
            int cin = cin0 + ci;
            float v = 0.f;
            if (cin < Cin && gr >= 0 && gr < HH && gc >= 0 && gc < WW)
                v = in[((size_t)img * Cin + cin) * HW + gr * WW + gc];
            sIn[ci][r][c] = v;
        }
        for (int idx = tid; idx < CHUNK * 9 * 16; idx += 256) {
            int ci  = idx / 144;
            int rem = idx - ci * 144;
            int k = rem >> 4, co = rem & 15;
            int cin = cin0 + ci;
            float v = 0.f;
            if (cin < Cin && (cob + co) < Cout)
                v = wt[((size_t)(cob + co) * Cin + cin) * 9 + k];
            sW[ci][k][co] = v;
        }
        __syncthreads();

        for (int ci = 0; ci < CHUNK; ci++) {
#pragma unroll
            for (int k = 0; k < 9; k++) {
                const int ky = k / 3, kx = k - ky * 3;
                const float4 w0 = *(const float4*)&sW[ci][k][0];
                const float4 w1 = *(const float4*)&sW[ci][k][4];
                const float4 w2 = *(const float4*)&sW[ci][k][8];
                const float4 w3 = *(const float4*)&sW[ci][k][12];
                const float wv[16] = {w0.x, w0.y, w0.z, w0.w, w1.x, w1.y, w1.z, w1.w,
                                      w2.x, w2.y, w2.z, w2.w, w3.x, w3.y, w3.z, w3.w};
#pragma unroll
                for (int p = 0; p < 4; p++) {
                    const float xv = sIn[ci][ty + ky][tx + 16 * p + kx];
#pragma unroll
                    for (int co = 0; co < 16; co++)
                        acc[p][co] = fmaf(xv, wv[co], acc[p][co]);
                }
            }
        }
        __syncthreads();
    }

    const int row = th * 16 + ty;
    const int colb2 = tw * 64 + tx;
#pragma unroll
    for (int co = 0; co < 16; co++) {
        const int oc = cob + co;
        if (oc < Cout) {
            const float b = bias[oc];
#pragma unroll
            for (int p = 0; p < 4; p++) {
                const size_t idx = ((size_t)img * Cout + oc) * HW + row * WW + colb2 + 16 * p;
                float v = acc[p][co] + b;
                if (addsrc) v += addsrc[idx];
                if (doRelu) v = fmaxf(v, 0.f);
                if (doRound) v = to_tf32(v);
                out[idx] = v;
            }
        }
    }
}

// ---------------- host launcher ----------------
static inline void launch_conv_ffma(const float* in, const float* w, const float* b,
                                    float* out, const float* add,
                                    int Cin, int Cout, int relu, int roundOut)
{
    dim3 grid(16, NIMG, (Cout + 15) / 16);
    conv3x3_kernel<<<grid, 256>>>(in, w, b, out, add, Cin, Cout, relu, roundOut);
}

static inline void launch_conv_tc(const float* in, const float* wp, const float* b,
                                  float* out, const float* add,
                                  int Cin, int Cout, int flags)
{
    dim3 grid(HH, NIMG, (Cout + 63) / 64);
    conv3x3_tc2<<<grid, 256>>>(in, wp, b, out, add, Cin, Cout, flags);
}

extern "C" void kernel_launch(void* const* d_in, const int* in_sizes, int n_in,
                              void* d_out, int out_size)
{
    const float* x       = (const float*)d_in[0];
    const float* w_init  = (const float*)d_in[1];
    const float* b_init  = (const float*)d_in[2];
    const float* res_w1  = (const float*)d_in[3];
    const float* res_b1  = (const float*)d_in[4];
    const float* res_w2  = (const float*)d_in[5];
    const float* res_b2  = (const float*)d_in[6];
    const float* w_bn    = (const float*)d_in[7];
    const float* b_bn    = (const float*)d_in[8];
    const float* off_w   = (const float*)d_in[9];
    const float* off_b   = (const float*)d_in[10];
    const float* com_w   = (const float*)d_in[11];
    const float* com_b   = (const float*)d_in[12];
    const float* dcn_w   = (const float*)d_in[13];
    const float* dcn_b   = (const float*)d_in[14];
    const float* w_rec   = (const float*)d_in[15];
    const float* b_rec   = (const float*)d_in[16];
    float* out = (float*)d_out;

    float *bufA, *bufB, *bufT, *obuf, *om, *wprep;
    cudaGetSymbolAddress((void**)&bufA, g_bufA);
    cudaGetSymbolAddress((void**)&bufB, g_bufB);
    cudaGetSymbolAddress((void**)&bufT, g_bufT);
    cudaGetSymbolAddress((void**)&obuf, g_off);
    cudaGetSymbolAddress((void**)&om,   g_om);
    cudaGetSymbolAddress((void**)&wprep, g_wprep);

    // ---- single fused weight prep ----
    prep_all_kernel<<<5184, 256>>>(res_w1, res_w2, w_bn, off_w, com_w, dcn_w, wprep);
    const float* pw_r1[5]; const float* pw_r2[5];
    for (int i = 0; i < 5; i++) { pw_r1[i] = wprep + (size_t)i * 36864; pw_r2[i] = wprep + (size_t)(5 + i) * 36864; }
    const float* pw_bn = wprep + 368640;
    const float* pw_off[4]; const float* pw_com[4]; const float* pw_gemm[4];
    for (int d = 0; d < 4; d++) {
        pw_off[d]  = wprep + 442368 + (size_t)d * 36864;
        pw_com[d]  = wprep + 589824 + (size_t)d * 147456;
        pw_gemm[d] = wprep + 1179648 + (size_t)d * 36864;
    }

    // ---- network ----
    // 1) init conv + relu (Cin=1, FFMA), round output to tf32
    launch_conv_ffma(x, w_init, b_init, bufA, nullptr, 1, 64, 1, 1);

    // 2) 5 residual blocks
    float* cur = bufA;
    float* nxt = bufB;
    for (int i = 0; i < 5; i++) {
        launch_conv_tc(cur, pw_r1[i], res_b1 + i * 64, bufT, nullptr, 64, 64, 1 | 2);
        launch_conv_tc(bufT, pw_r2[i], res_b2 + i * 64, nxt, cur, 64, 64, 2);
        float* t = cur; cur = nxt; nxt = t;
    }
    float* feat = cur;

    // 3) bottleneck conv over [ref | nei] (cat folded into loads)
    launch_conv_tc(feat, pw_bn, b_bn, bufA, nullptr, 128, 64, 2 | 4);

    // 4) four chained DCN stages
    dim3 ggemm(HW / 128, NIMG);
    auto dcn_stage = [&](const float* xsrc, const float* feaSrc, int di, float* outBuf) {
        launch_conv_tc(feaSrc, pw_off[di], off_b + di * 64, obuf, nullptr, 64, 64, 2);
        launch_conv_tc(obuf, pw_com[di], com_b + di * 216, om, nullptr, 64, 216, 0);
        dcn_fused_kernel<<<ggemm, 256>>>(pw_gemm[di], xsrc, om, dcn_b + di * 64, outBuf);
    };

    dcn_stage(bufA, bufA, 0, bufT);   // fea = dcn(fea, o0)
    dcn_stage(bufT, bufT, 1, bufA);   // fea = dcn(fea, o1)
    dcn_stage(feat, bufA, 2, bufT);   // fea = dcn(nei, o2)
    dcn_stage(bufT, bufT, 3, bufA);   // aligned = dcn(fea, o3)

    // 5) reconstruction conv (Cout=1, FFMA) straight into d_out
    launch_conv_ffma(bufA, w_rec, b_rec, out, nullptr, 64, 1, 0, 0);
}